// round 1
// baseline (speedup 1.0000x reference)
#include <cuda_runtime.h>
#include <cuda_bf16.h>
#include <math.h>

#define B_   2048
#define A_   256
#define ED_  200
#define RD_  200
#define HD_  400
#define XD_  800
#define AD_  400
#define HUGE_ 1e9f

__device__ float g_X [B_ * XD_];
__device__ float g_h1[B_ * AD_];
__device__ float g_X2[B_ * AD_];

__global__ void build_X_kernel(const int* __restrict__ e,
                               const int* __restrict__ q,
                               const float* __restrict__ H,
                               const float* __restrict__ ent_emb,
                               const float* __restrict__ rel_emb) {
    int b = blockIdx.x;
    int ei = e[b];
    int qi = q[b];
    const float* erow = ent_emb + (long)ei * ED_;
    const float* qrow = rel_emb + (long)qi * RD_;
    const float* hrow = H + (long)b * HD_;
    float* xrow = g_X + (long)b * XD_;
    for (int i = threadIdx.x; i < XD_; i += blockDim.x) {
        float v;
        if (i < ED_)            v = erow[i];
        else if (i < ED_ + HD_) v = hrow[i - ED_];
        else                    v = qrow[i - ED_ - HD_];
        xrow[i] = v;
    }
}

// STAGE: 0 -> A=g_X,  C=g_h1, K=800, ReLU
//        1 -> A=g_h1, C=g_X2, K=400, no ReLU
template<int STAGE>
__global__ void sgemm_kernel(const float* __restrict__ Bm,
                             const float* __restrict__ bias) {
    const int K = (STAGE == 0) ? XD_ : AD_;
    const int N = AD_;
    const float* A = (STAGE == 0) ? g_X : g_h1;
    float* C       = (STAGE == 0) ? g_h1 : g_X2;

    __shared__ float As[16][64];
    __shared__ float Bs[16][64];

    const int tid = threadIdx.x;
    const int tx = tid & 15;
    const int ty = tid >> 4;
    const int bm = blockIdx.y * 64;
    const int bn = blockIdx.x * 64;

    float acc[4][4] = {};

    for (int k0 = 0; k0 < K; k0 += 16) {
        {
            int ar = tid >> 2;
            int ac = (tid & 3) << 2;
            float4 v = *reinterpret_cast<const float4*>(&A[(long)(bm + ar) * K + k0 + ac]);
            As[ac + 0][ar] = v.x;
            As[ac + 1][ar] = v.y;
            As[ac + 2][ar] = v.z;
            As[ac + 3][ar] = v.w;
        }
        {
            int br = tid >> 4;
            int bc = (tid & 15) << 2;
            int n = bn + bc;
            float4 v;
            if (n + 3 < N) {
                v = *reinterpret_cast<const float4*>(&Bm[(long)(k0 + br) * N + n]);
            } else {
                v.x = (n + 0 < N) ? Bm[(long)(k0 + br) * N + n + 0] : 0.f;
                v.y = (n + 1 < N) ? Bm[(long)(k0 + br) * N + n + 1] : 0.f;
                v.z = (n + 2 < N) ? Bm[(long)(k0 + br) * N + n + 2] : 0.f;
                v.w = 0.f;
            }
            Bs[br][bc + 0] = v.x;
            Bs[br][bc + 1] = v.y;
            Bs[br][bc + 2] = v.z;
            Bs[br][bc + 3] = v.w;
        }
        __syncthreads();

        #pragma unroll
        for (int k = 0; k < 16; k++) {
            float4 av = *reinterpret_cast<const float4*>(&As[k][ty << 2]);
            float4 bv = *reinterpret_cast<const float4*>(&Bs[k][tx << 2]);
            float am[4] = {av.x, av.y, av.z, av.w};
            float bnv[4] = {bv.x, bv.y, bv.z, bv.w};
            #pragma unroll
            for (int i = 0; i < 4; i++)
                #pragma unroll
                for (int j = 0; j < 4; j++)
                    acc[i][j] += am[i] * bnv[j];
        }
        __syncthreads();
    }

    #pragma unroll
    for (int i = 0; i < 4; i++) {
        int m = bm + (ty << 2) + i;
        #pragma unroll
        for (int j = 0; j < 4; j++) {
            int n = bn + (tx << 2) + j;
            if (n < N) {
                float c = acc[i][j] + bias[n];
                if (STAGE == 0) c = fmaxf(c, 0.f);
                C[(long)m * N + n] = c;
            }
        }
    }
}

__global__ void score_kernel(const int* __restrict__ r_space,
                             const int* __restrict__ e_space,
                             const int* __restrict__ action_mask,
                             const float* __restrict__ rel_emb,
                             const float* __restrict__ ent_emb,
                             float* __restrict__ out_dist,
                             float* __restrict__ out_ent) {
    const int b = blockIdx.x;
    const int tid = threadIdx.x;
    const int lane = tid & 31;
    const int warp = tid >> 5;

    __shared__ float x2s[AD_];
    __shared__ float sc[A_];
    __shared__ float red[8];

    for (int i = tid; i < AD_; i += 256) x2s[i] = g_X2[(long)b * AD_ + i];
    __syncthreads();

    const long base = (long)b * A_;
    for (int i = 0; i < 32; i++) {
        int a = warp * 32 + i;
        int rr = r_space[base + a];
        int er = e_space[base + a];
        const float* rrow = rel_emb + (long)rr * RD_;
        const float* erow = ent_emb + (long)er * ED_;
        float s = 0.f;
        for (int j = lane; j < RD_; j += 32)
            s += rrow[j] * x2s[j] + erow[j] * x2s[RD_ + j];
        #pragma unroll
        for (int o = 16; o; o >>= 1) s += __shfl_xor_sync(0xffffffffu, s, o);
        if (lane == 0) {
            float m = (float)action_mask[base + a];
            sc[a] = s - (1.0f - m) * HUGE_;
        }
    }
    __syncthreads();

    float v = sc[tid];

    float mx = v;
    #pragma unroll
    for (int o = 16; o; o >>= 1) mx = fmaxf(mx, __shfl_xor_sync(0xffffffffu, mx, o));
    if (lane == 0) red[warp] = mx;
    __syncthreads();
    if (warp == 0) {
        float mm = red[lane & 7];
        #pragma unroll
        for (int o = 4; o; o >>= 1) mm = fmaxf(mm, __shfl_xor_sync(0xffffffffu, mm, o));
        if (lane == 0) red[0] = mm;
    }
    __syncthreads();
    mx = red[0];
    __syncthreads();

    float ev = expf(v - mx);
    float sm = ev;
    #pragma unroll
    for (int o = 16; o; o >>= 1) sm += __shfl_xor_sync(0xffffffffu, sm, o);
    if (lane == 0) red[warp] = sm;
    __syncthreads();
    if (warp == 0) {
        float ss = red[lane & 7];
        #pragma unroll
        for (int o = 4; o; o >>= 1) ss += __shfl_xor_sync(0xffffffffu, ss, o);
        if (lane == 0) red[0] = ss;
    }
    __syncthreads();
    float total = red[0];
    __syncthreads();

    float p = ev / total;
    out_dist[base + tid] = p;

    float t = p * logf(fmaxf(p, 1e-20f));
    float es = t;
    #pragma unroll
    for (int o = 16; o; o >>= 1) es += __shfl_xor_sync(0xffffffffu, es, o);
    if (lane == 0) red[warp] = es;
    __syncthreads();
    if (warp == 0) {
        float ss = red[lane & 7];
        #pragma unroll
        for (int o = 4; o; o >>= 1) ss += __shfl_xor_sync(0xffffffffu, ss, o);
        if (lane == 0) out_ent[b] = -ss;
    }
}

extern "C" void kernel_launch(void* const* d_in, const int* in_sizes, int n_in,
                              void* d_out, int out_size) {
    const int*   e        = (const int*)  d_in[0];
    const int*   q        = (const int*)  d_in[1];
    const int*   r_space  = (const int*)  d_in[2];
    const int*   e_space  = (const int*)  d_in[3];
    const int*   mask     = (const int*)  d_in[4];
    const float* H        = (const float*)d_in[5];
    const float* ent_emb  = (const float*)d_in[6];
    const float* rel_emb  = (const float*)d_in[7];
    const float* W1       = (const float*)d_in[8];
    const float* b1       = (const float*)d_in[9];
    const float* W2       = (const float*)d_in[10];
    const float* b2       = (const float*)d_in[11];

    float* out_dist = (float*)d_out;
    float* out_ent  = (float*)d_out + (long)B_ * A_;

    build_X_kernel<<<B_, 256>>>(e, q, H, ent_emb, rel_emb);

    dim3 grid((AD_ + 63) / 64, B_ / 64);   // 7 x 32
    sgemm_kernel<0><<<grid, 256>>>(W1, b1);
    sgemm_kernel<1><<<grid, 256>>>(W2, b2);

    score_kernel<<<B_, 256>>>(r_space, e_space, mask, rel_emb, ent_emb,
                              out_dist, out_ent);
}

// round 2
// speedup vs baseline: 1.3183x; 1.3183x over previous
#include <cuda_runtime.h>
#include <cuda_bf16.h>
#include <math.h>

#define B_   2048
#define A_   256
#define ED_  200
#define RD_  200
#define HD_  400
#define XD_  800
#define AD_  400
#define HUGE_ 1e9f

__device__ float g_X [B_ * XD_];
__device__ float g_h1[B_ * AD_];
__device__ float g_X2[B_ * AD_];

__global__ void build_X_kernel(const int* __restrict__ e,
                               const int* __restrict__ q,
                               const float* __restrict__ H,
                               const float* __restrict__ ent_emb,
                               const float* __restrict__ rel_emb) {
    int b = blockIdx.x;
    int ei = e[b];
    int qi = q[b];
    const float* erow = ent_emb + (long)ei * ED_;
    const float* qrow = rel_emb + (long)qi * RD_;
    const float* hrow = H + (long)b * HD_;
    float* xrow = g_X + (long)b * XD_;
    for (int i = threadIdx.x; i < XD_; i += blockDim.x) {
        float v;
        if (i < ED_)            v = erow[i];
        else if (i < ED_ + HD_) v = hrow[i - ED_];
        else                    v = qrow[i - ED_ - HD_];
        xrow[i] = v;
    }
}

// STAGE: 0 -> A=g_X,  C=g_h1, K=800, ReLU
//        1 -> A=g_h1, C=g_X2, K=400, no ReLU
template<int STAGE>
__global__ void sgemm_kernel(const float* __restrict__ Bm,
                             const float* __restrict__ bias) {
    const int K = (STAGE == 0) ? XD_ : AD_;
    const int N = AD_;
    const float* A = (STAGE == 0) ? g_X : g_h1;
    float* C       = (STAGE == 0) ? g_h1 : g_X2;

    __shared__ float As[16][64];
    __shared__ float Bs[16][64];

    const int tid = threadIdx.x;
    const int tx = tid & 15;
    const int ty = tid >> 4;
    const int bm = blockIdx.y * 64;
    const int bn = blockIdx.x * 64;

    float acc[4][4] = {};

    for (int k0 = 0; k0 < K; k0 += 16) {
        {
            int ar = tid >> 2;
            int ac = (tid & 3) << 2;
            float4 v = *reinterpret_cast<const float4*>(&A[(long)(bm + ar) * K + k0 + ac]);
            As[ac + 0][ar] = v.x;
            As[ac + 1][ar] = v.y;
            As[ac + 2][ar] = v.z;
            As[ac + 3][ar] = v.w;
        }
        {
            int br = tid >> 4;
            int bc = (tid & 15) << 2;
            int n = bn + bc;
            float4 v;
            if (n + 3 < N) {
                v = *reinterpret_cast<const float4*>(&Bm[(long)(k0 + br) * N + n]);
            } else {
                v.x = (n + 0 < N) ? Bm[(long)(k0 + br) * N + n + 0] : 0.f;
                v.y = (n + 1 < N) ? Bm[(long)(k0 + br) * N + n + 1] : 0.f;
                v.z = (n + 2 < N) ? Bm[(long)(k0 + br) * N + n + 2] : 0.f;
                v.w = 0.f;
            }
            Bs[br][bc + 0] = v.x;
            Bs[br][bc + 1] = v.y;
            Bs[br][bc + 2] = v.z;
            Bs[br][bc + 3] = v.w;
        }
        __syncthreads();

        #pragma unroll
        for (int k = 0; k < 16; k++) {
            float4 av = *reinterpret_cast<const float4*>(&As[k][ty << 2]);
            float4 bv = *reinterpret_cast<const float4*>(&Bs[k][tx << 2]);
            float am[4] = {av.x, av.y, av.z, av.w};
            float bnv[4] = {bv.x, bv.y, bv.z, bv.w};
            #pragma unroll
            for (int i = 0; i < 4; i++)
                #pragma unroll
                for (int j = 0; j < 4; j++)
                    acc[i][j] += am[i] * bnv[j];
        }
        __syncthreads();
    }

    #pragma unroll
    for (int i = 0; i < 4; i++) {
        int m = bm + (ty << 2) + i;
        #pragma unroll
        for (int j = 0; j < 4; j++) {
            int n = bn + (tx << 2) + j;
            if (n < N) {
                float c = acc[i][j] + bias[n];
                if (STAGE == 0) c = fmaxf(c, 0.f);
                C[(long)m * N + n] = c;
            }
        }
    }
}

__device__ __forceinline__ float dot4(float4 a, float4 b) {
    return a.x * b.x + a.y * b.y + a.z * b.z + a.w * b.w;
}

// One block per batch row. 8 warps x 32 actions.
// Vectorized float4 gather, 2 actions in flight per warp iteration.
__global__ void score_kernel(const int* __restrict__ r_space,
                             const int* __restrict__ e_space,
                             const int* __restrict__ action_mask,
                             const float* __restrict__ rel_emb,
                             const float* __restrict__ ent_emb,
                             float* __restrict__ out_dist,
                             float* __restrict__ out_ent) {
    const int b = blockIdx.x;
    const int tid = threadIdx.x;
    const int lane = tid & 31;
    const int warp = tid >> 5;
    const unsigned FULL = 0xffffffffu;

    __shared__ float4 x2a[100];   // [0..49] = rel half of X2, [50..99] = ent half
    __shared__ float sc[A_];
    __shared__ float red[8];

    if (tid < 100)
        x2a[tid] = reinterpret_cast<const float4*>(g_X2 + (long)b * AD_)[tid];
    __syncthreads();

    const long base = (long)b * A_;

    // preload this warp's 32 action indices + masks into registers
    const int aidx = warp * 32 + lane;
    const int my_r = r_space[base + aidx];
    const int my_e = e_space[base + aidx];
    const int my_m = action_mask[base + aidx];

    const float4 xr0 = x2a[lane];        // j = lane   (<50 always)
    const float4 xe0 = x2a[50 + lane];
    const bool hi = (lane < 18);
    const float4 xr1 = hi ? x2a[32 + lane] : make_float4(0.f, 0.f, 0.f, 0.f);
    const float4 xe1 = hi ? x2a[82 + lane] : make_float4(0.f, 0.f, 0.f, 0.f);

    #pragma unroll
    for (int i = 0; i < 32; i += 2) {
        int rr0 = __shfl_sync(FULL, my_r, i);
        int ee0 = __shfl_sync(FULL, my_e, i);
        int rr1 = __shfl_sync(FULL, my_r, i + 1);
        int ee1 = __shfl_sync(FULL, my_e, i + 1);

        const float4* r0 = reinterpret_cast<const float4*>(rel_emb + (long)rr0 * RD_);
        const float4* e0 = reinterpret_cast<const float4*>(ent_emb + (long)ee0 * ED_);
        const float4* r1 = reinterpret_cast<const float4*>(rel_emb + (long)rr1 * RD_);
        const float4* e1 = reinterpret_cast<const float4*>(ent_emb + (long)ee1 * ED_);

        // issue all low-half loads first (8 independent 16B loads)
        float4 rv0a = r0[lane];
        float4 ev0a = e0[lane];
        float4 rv1a = r1[lane];
        float4 ev1a = e1[lane];

        float s0 = dot4(rv0a, xr0) + dot4(ev0a, xe0);
        float s1 = dot4(rv1a, xr0) + dot4(ev1a, xe0);

        if (hi) {
            float4 rv0b = r0[32 + lane];
            float4 ev0b = e0[32 + lane];
            float4 rv1b = r1[32 + lane];
            float4 ev1b = e1[32 + lane];
            s0 += dot4(rv0b, xr1) + dot4(ev0b, xe1);
            s1 += dot4(rv1b, xr1) + dot4(ev1b, xe1);
        }

        #pragma unroll
        for (int o = 16; o; o >>= 1) {
            s0 += __shfl_xor_sync(FULL, s0, o);
            s1 += __shfl_xor_sync(FULL, s1, o);
        }
        if (lane == i) sc[warp * 32 + i] = s0 - (1.0f - (float)my_m) * HUGE_;
        if (lane == i + 1) sc[warp * 32 + i + 1] = s1 - (1.0f - (float)my_m) * HUGE_;
    }
    __syncthreads();

    float v = sc[tid];

    // block max
    float mx = v;
    #pragma unroll
    for (int o = 16; o; o >>= 1) mx = fmaxf(mx, __shfl_xor_sync(FULL, mx, o));
    if (lane == 0) red[warp] = mx;
    __syncthreads();
    if (warp == 0) {
        float mm = red[lane & 7];
        #pragma unroll
        for (int o = 4; o; o >>= 1) mm = fmaxf(mm, __shfl_xor_sync(FULL, mm, o));
        if (lane == 0) red[0] = mm;
    }
    __syncthreads();
    mx = red[0];
    __syncthreads();

    // exp + sum
    float ev = expf(v - mx);
    float sm = ev;
    #pragma unroll
    for (int o = 16; o; o >>= 1) sm += __shfl_xor_sync(FULL, sm, o);
    if (lane == 0) red[warp] = sm;
    __syncthreads();
    if (warp == 0) {
        float ss = red[lane & 7];
        #pragma unroll
        for (int o = 4; o; o >>= 1) ss += __shfl_xor_sync(FULL, ss, o);
        if (lane == 0) red[0] = ss;
    }
    __syncthreads();
    float total = red[0];
    __syncthreads();

    float p = ev / total;
    out_dist[base + tid] = p;

    // entropy
    float t = p * logf(fmaxf(p, 1e-20f));
    float es = t;
    #pragma unroll
    for (int o = 16; o; o >>= 1) es += __shfl_xor_sync(FULL, es, o);
    if (lane == 0) red[warp] = es;
    __syncthreads();
    if (warp == 0) {
        float ss = red[lane & 7];
        #pragma unroll
        for (int o = 4; o; o >>= 1) ss += __shfl_xor_sync(FULL, ss, o);
        if (lane == 0) out_ent[b] = -ss;
    }
}

extern "C" void kernel_launch(void* const* d_in, const int* in_sizes, int n_in,
                              void* d_out, int out_size) {
    const int*   e        = (const int*)  d_in[0];
    const int*   q        = (const int*)  d_in[1];
    const int*   r_space  = (const int*)  d_in[2];
    const int*   e_space  = (const int*)  d_in[3];
    const int*   mask     = (const int*)  d_in[4];
    const float* H        = (const float*)d_in[5];
    const float* ent_emb  = (const float*)d_in[6];
    const float* rel_emb  = (const float*)d_in[7];
    const float* W1       = (const float*)d_in[8];
    const float* b1       = (const float*)d_in[9];
    const float* W2       = (const float*)d_in[10];
    const float* b2       = (const float*)d_in[11];

    float* out_dist = (float*)d_out;
    float* out_ent  = (float*)d_out + (long)B_ * A_;

    build_X_kernel<<<B_, 256>>>(e, q, H, ent_emb, rel_emb);

    dim3 grid((AD_ + 63) / 64, B_ / 64);   // 7 x 32
    sgemm_kernel<0><<<grid, 256>>>(W1, b1);
    sgemm_kernel<1><<<grid, 256>>>(W2, b2);

    score_kernel<<<B_, 256>>>(r_space, e_space, mask, rel_emb, ent_emb,
                              out_dist, out_ent);
}

// round 3
// speedup vs baseline: 1.4041x; 1.0651x over previous
#include <cuda_runtime.h>
#include <cuda_bf16.h>
#include <math.h>

#define B_   2048
#define A_   256
#define ED_  200
#define RD_  200
#define HD_  400
#define XD_  800
#define AD_  400
#define HUGE_ 1e9f

__device__ float g_X [B_ * XD_];
__device__ float g_h1[B_ * AD_];
__device__ float g_X2[B_ * AD_];

__global__ void build_X_kernel(const int* __restrict__ e,
                               const int* __restrict__ q,
                               const float* __restrict__ H,
                               const float* __restrict__ ent_emb,
                               const float* __restrict__ rel_emb) {
    int b = blockIdx.x;
    int ei = e[b];
    int qi = q[b];
    const float* erow = ent_emb + (long)ei * ED_;
    const float* qrow = rel_emb + (long)qi * RD_;
    const float* hrow = H + (long)b * HD_;
    float* xrow = g_X + (long)b * XD_;
    for (int i = threadIdx.x; i < XD_; i += blockDim.x) {
        float v;
        if (i < ED_)            v = erow[i];
        else if (i < ED_ + HD_) v = hrow[i - ED_];
        else                    v = qrow[i - ED_ - HD_];
        xrow[i] = v;
    }
}

// ---------------------------------------------------------------------------
// Double-buffered SGEMM. 64x64 tile, k-tile 16, 256 threads, 4x4/thread.
// One __syncthreads per k-tile; global prefetch overlaps FMA block.
// STAGE: 0 -> A=g_X,  C=g_h1, K=800, ReLU; 1 -> A=g_h1, C=g_X2, K=400
// ---------------------------------------------------------------------------
template<int STAGE>
__global__ void sgemm_kernel(const float* __restrict__ Bm,
                             const float* __restrict__ bias) {
    const int K = (STAGE == 0) ? XD_ : AD_;
    const int N = AD_;
    const float* A = (STAGE == 0) ? g_X : g_h1;
    float* C       = (STAGE == 0) ? g_h1 : g_X2;

    __shared__ float As[2][16][64];
    __shared__ float Bs[2][16][64];

    const int tid = threadIdx.x;
    const int tx = tid & 15;
    const int ty = tid >> 4;
    const int bm = blockIdx.y * 64;
    const int bn = blockIdx.x * 64;

    // loader coordinates
    const int ar = tid >> 2;            // A row in tile (0..63)
    const int ac = (tid & 3) << 2;      // A col in k-tile (0,4,8,12)
    const int br = tid >> 4;            // B row in k-tile (0..15)
    const int bc = (tid & 15) << 2;     // B col in tile (0..60)

    float acc[4][4] = {};

    const int nt = K / 16;

    // helper lambdas (inlined)
    auto loadA = [&](int t) -> float4 {
        return *reinterpret_cast<const float4*>(&A[(long)(bm + ar) * K + t * 16 + ac]);
    };
    auto loadB = [&](int t) -> float4 {
        int n = bn + bc;
        if (n + 3 < N) {
            return *reinterpret_cast<const float4*>(&Bm[(long)(t * 16 + br) * N + n]);
        } else {
            float4 v;
            v.x = (n + 0 < N) ? Bm[(long)(t * 16 + br) * N + n + 0] : 0.f;
            v.y = (n + 1 < N) ? Bm[(long)(t * 16 + br) * N + n + 1] : 0.f;
            v.z = (n + 2 < N) ? Bm[(long)(t * 16 + br) * N + n + 2] : 0.f;
            v.w = 0.f;
            return v;
        }
    };

    // preload tile 0
    {
        float4 va = loadA(0);
        float4 vb = loadB(0);
        As[0][ac + 0][ar] = va.x;
        As[0][ac + 1][ar] = va.y;
        As[0][ac + 2][ar] = va.z;
        As[0][ac + 3][ar] = va.w;
        Bs[0][br][bc + 0] = vb.x;
        Bs[0][br][bc + 1] = vb.y;
        Bs[0][br][bc + 2] = vb.z;
        Bs[0][br][bc + 3] = vb.w;
    }
    __syncthreads();

    for (int t = 0; t < nt; t++) {
        const int cur = t & 1;
        float4 pa, pb;
        const bool more = (t + 1 < nt);
        if (more) {
            pa = loadA(t + 1);
            pb = loadB(t + 1);
        }

        #pragma unroll
        for (int k = 0; k < 16; k++) {
            float4 av = *reinterpret_cast<const float4*>(&As[cur][k][ty << 2]);
            float4 bv = *reinterpret_cast<const float4*>(&Bs[cur][k][tx << 2]);
            float am[4] = {av.x, av.y, av.z, av.w};
            float bnv[4] = {bv.x, bv.y, bv.z, bv.w};
            #pragma unroll
            for (int i = 0; i < 4; i++)
                #pragma unroll
                for (int j = 0; j < 4; j++)
                    acc[i][j] += am[i] * bnv[j];
        }

        if (more) {
            const int nxt = cur ^ 1;
            As[nxt][ac + 0][ar] = pa.x;
            As[nxt][ac + 1][ar] = pa.y;
            As[nxt][ac + 2][ar] = pa.z;
            As[nxt][ac + 3][ar] = pa.w;
            Bs[nxt][br][bc + 0] = pb.x;
            Bs[nxt][br][bc + 1] = pb.y;
            Bs[nxt][br][bc + 2] = pb.z;
            Bs[nxt][br][bc + 3] = pb.w;
        }
        __syncthreads();
    }

    #pragma unroll
    for (int i = 0; i < 4; i++) {
        int m = bm + (ty << 2) + i;
        #pragma unroll
        for (int j = 0; j < 4; j++) {
            int n = bn + (tx << 2) + j;
            if (n < N) {
                float c = acc[i][j] + bias[n];
                if (STAGE == 0) c = fmaxf(c, 0.f);
                C[(long)m * N + n] = c;
            }
        }
    }
}

__device__ __forceinline__ float dot4(float4 a, float4 b) {
    return a.x * b.x + a.y * b.y + a.z * b.z + a.w * b.w;
}

// One block per batch row. 8 warps x 32 actions, 2 actions per iteration.
// launch_bounds(256,6): cap regs so 6 blocks/SM fit -> occupancy ~70%.
__global__ void __launch_bounds__(256, 6)
score_kernel(const int* __restrict__ r_space,
             const int* __restrict__ e_space,
             const int* __restrict__ action_mask,
             const float* __restrict__ rel_emb,
             const float* __restrict__ ent_emb,
             float* __restrict__ out_dist,
             float* __restrict__ out_ent) {
    const int b = blockIdx.x;
    const int tid = threadIdx.x;
    const int lane = tid & 31;
    const int warp = tid >> 5;
    const unsigned FULL = 0xffffffffu;

    __shared__ float4 x2a[100];   // [0..49] rel half of X2, [50..99] ent half
    __shared__ float sc[A_];
    __shared__ float red[8];

    if (tid < 100)
        x2a[tid] = reinterpret_cast<const float4*>(g_X2 + (long)b * AD_)[tid];
    __syncthreads();

    const long base = (long)b * A_;

    const int aidx = warp * 32 + lane;
    const int my_r = r_space[base + aidx];
    const int my_e = e_space[base + aidx];
    const int my_m = action_mask[base + aidx];

    const float4 xr0 = x2a[lane];
    const float4 xe0 = x2a[50 + lane];
    const bool hi = (lane < 18);

    #pragma unroll
    for (int i = 0; i < 32; i += 2) {
        int rr0 = __shfl_sync(FULL, my_r, i);
        int ee0 = __shfl_sync(FULL, my_e, i);
        int rr1 = __shfl_sync(FULL, my_r, i + 1);
        int ee1 = __shfl_sync(FULL, my_e, i + 1);

        const float4* r0 = reinterpret_cast<const float4*>(rel_emb + (long)rr0 * RD_);
        const float4* e0 = reinterpret_cast<const float4*>(ent_emb + (long)ee0 * ED_);
        const float4* r1 = reinterpret_cast<const float4*>(rel_emb + (long)rr1 * RD_);
        const float4* e1 = reinterpret_cast<const float4*>(ent_emb + (long)ee1 * ED_);

        float4 rv0a = r0[lane];
        float4 ev0a = e0[lane];
        float4 rv1a = r1[lane];
        float4 ev1a = e1[lane];

        float s0 = dot4(rv0a, xr0) + dot4(ev0a, xe0);
        float s1 = dot4(rv1a, xr0) + dot4(ev1a, xe0);

        if (hi) {
            float4 rv0b = r0[32 + lane];
            float4 ev0b = e0[32 + lane];
            float4 rv1b = r1[32 + lane];
            float4 ev1b = e1[32 + lane];
            // hi-half X2 fragments from smem (loop-invariant; keep out of regs)
            float4 xr1 = x2a[32 + lane];
            float4 xe1 = x2a[82 + lane];
            s0 += dot4(rv0b, xr1) + dot4(ev0b, xe1);
            s1 += dot4(rv1b, xr1) + dot4(ev1b, xe1);
        }

        #pragma unroll
        for (int o = 16; o; o >>= 1) {
            s0 += __shfl_xor_sync(FULL, s0, o);
            s1 += __shfl_xor_sync(FULL, s1, o);
        }
        if (lane == i) sc[warp * 32 + i] = s0 - (1.0f - (float)my_m) * HUGE_;
        if (lane == i + 1) sc[warp * 32 + i + 1] = s1 - (1.0f - (float)my_m) * HUGE_;
    }
    __syncthreads();

    float v = sc[tid];

    float mx = v;
    #pragma unroll
    for (int o = 16; o; o >>= 1) mx = fmaxf(mx, __shfl_xor_sync(FULL, mx, o));
    if (lane == 0) red[warp] = mx;
    __syncthreads();
    if (warp == 0) {
        float mm = red[lane & 7];
        #pragma unroll
        for (int o = 4; o; o >>= 1) mm = fmaxf(mm, __shfl_xor_sync(FULL, mm, o));
        if (lane == 0) red[0] = mm;
    }
    __syncthreads();
    mx = red[0];
    __syncthreads();

    float ev = expf(v - mx);
    float sm = ev;
    #pragma unroll
    for (int o = 16; o; o >>= 1) sm += __shfl_xor_sync(FULL, sm, o);
    if (lane == 0) red[warp] = sm;
    __syncthreads();
    if (warp == 0) {
        float ss = red[lane & 7];
        #pragma unroll
        for (int o = 4; o; o >>= 1) ss += __shfl_xor_sync(FULL, ss, o);
        if (lane == 0) red[0] = ss;
    }
    __syncthreads();
    float total = red[0];
    __syncthreads();

    float p = ev / total;
    out_dist[base + tid] = p;

    float t = p * logf(fmaxf(p, 1e-20f));
    float es = t;
    #pragma unroll
    for (int o = 16; o; o >>= 1) es += __shfl_xor_sync(FULL, es, o);
    if (lane == 0) red[warp] = es;
    __syncthreads();
    if (warp == 0) {
        float ss = red[lane & 7];
        #pragma unroll
        for (int o = 4; o; o >>= 1) ss += __shfl_xor_sync(FULL, ss, o);
        if (lane == 0) out_ent[b] = -ss;
    }
}

extern "C" void kernel_launch(void* const* d_in, const int* in_sizes, int n_in,
                              void* d_out, int out_size) {
    const int*   e        = (const int*)  d_in[0];
    const int*   q        = (const int*)  d_in[1];
    const int*   r_space  = (const int*)  d_in[2];
    const int*   e_space  = (const int*)  d_in[3];
    const int*   mask     = (const int*)  d_in[4];
    const float* H        = (const float*)d_in[5];
    const float* ent_emb  = (const float*)d_in[6];
    const float* rel_emb  = (const float*)d_in[7];
    const float* W1       = (const float*)d_in[8];
    const float* b1       = (const float*)d_in[9];
    const float* W2       = (const float*)d_in[10];
    const float* b2       = (const float*)d_in[11];

    float* out_dist = (float*)d_out;
    float* out_ent  = (float*)d_out + (long)B_ * A_;

    build_X_kernel<<<B_, 256>>>(e, q, H, ent_emb, rel_emb);

    dim3 grid((AD_ + 63) / 64, B_ / 64);   // 7 x 32
    sgemm_kernel<0><<<grid, 256>>>(W1, b1);
    sgemm_kernel<1><<<grid, 256>>>(W2, b2);

    score_kernel<<<B_, 256>>>(r_space, e_space, mask, rel_emb, ent_emb,
                              out_dist, out_ent);
}